// round 12
// baseline (speedup 1.0000x reference)
#include <cuda_runtime.h>
#include <cuda_fp16.h>
#include <cstdint>

// Problem constants
#define BB 2
#define NN 2048
#define CC 1024
#define HH 16
#define MM (BB * NN)            // 4096 rows
#define SL2E 0.04506933791622f  // (1/32) * log2(e)

// ---------------------------------------------------------------------------
// Scratch (device globals; no allocation allowed)
// ---------------------------------------------------------------------------
__device__ __half g_q16[MM * CC];                 // queries fp16
__device__ __half g_x16[MM * CC];                 // x fp16
__device__ __half g_wq16[CC * CC], g_wk16[CC * CC], g_wv16[CC * CC], g_wo16[CC * CC];
__device__ __half g_ao16[MM * CC];                // attention out fp16
__device__ __half g_Qp[MM * CC], g_Kp[MM * CC];   // projected Q (pre-scaled), K
__device__ __half g_V16[MM * CC];                 // projected V (fp16)

// ---------------------------------------------------------------------------
// Helpers (portable PTX only: mma.sync / ldmatrix / cp.async)
// ---------------------------------------------------------------------------
__device__ __forceinline__ uint32_t smem_u32(const void* p) {
    uint32_t a;
    asm("{ .reg .u64 t; cvta.to.shared.u64 t, %1; cvt.u32.u64 %0, t; }"
        : "=r"(a) : "l"(p));
    return a;
}

#define CP_ASYNC_16(dst, src) \
    asm volatile("cp.async.cg.shared.global [%0], [%1], 16;" :: "r"(dst), "l"(src))
#define CP_COMMIT() asm volatile("cp.async.commit_group;" ::: "memory")
#define CP_WAIT(n)  asm volatile("cp.async.wait_group %0;" :: "n"(n) : "memory")

__device__ __forceinline__ void ldsm4(uint32_t* r, uint32_t a) {
    asm volatile("ldmatrix.sync.aligned.m8n8.x4.shared.b16 {%0,%1,%2,%3}, [%4];"
        : "=r"(r[0]), "=r"(r[1]), "=r"(r[2]), "=r"(r[3]) : "r"(a));
}
__device__ __forceinline__ void ldsm4t(uint32_t* r, uint32_t a) {
    asm volatile("ldmatrix.sync.aligned.m8n8.x4.trans.shared.b16 {%0,%1,%2,%3}, [%4];"
        : "=r"(r[0]), "=r"(r[1]), "=r"(r[2]), "=r"(r[3]) : "r"(a));
}

__device__ __forceinline__ void mma16816(float* c, const uint32_t* a,
                                         uint32_t b0, uint32_t b1) {
    asm volatile(
        "mma.sync.aligned.m16n8k16.row.col.f32.f16.f16.f32 "
        "{%0,%1,%2,%3}, {%4,%5,%6,%7}, {%8,%9}, {%0,%1,%2,%3};"
        : "+f"(c[0]), "+f"(c[1]), "+f"(c[2]), "+f"(c[3])
        : "r"(a[0]), "r"(a[1]), "r"(a[2]), "r"(a[3]), "r"(b0), "r"(b1));
}

__device__ __forceinline__ uint32_t pkh2(float a, float b) {
    __half2 h = __floats2half2_rn(a, b);
    return *reinterpret_cast<uint32_t*>(&h);
}

// exp2 on a packed half2 pair (one MUFU op for two values)
__device__ __forceinline__ uint32_t h2ex2(uint32_t x) {
    uint32_t y;
    asm("ex2.approx.f16x2 %0, %1;" : "=r"(y) : "r"(x));
    return y;
}

// SW128 for 128-byte rows: SW128(row*128 + c) = row*128 + (c ^ ((row&7)<<4))
__device__ __forceinline__ uint32_t sw_row128(uint32_t row, uint32_t cbytes) {
    return row * 128u + (cbytes ^ ((row & 7u) << 4));
}

// ---------------------------------------------------------------------------
// fp32 -> fp16 conversion: ALL tensors, 4 float4 per thread (MLP=4).
// Segments (float4 units): [0,1M) x | [1M,2M) q | [2M..3M) wq,wk,wv,wo.
// ---------------------------------------------------------------------------
__global__ __launch_bounds__(256) void cvt_all_k(
    const float* __restrict__ x, const float* __restrict__ q,
    const float* __restrict__ wq, const float* __restrict__ wk,
    const float* __restrict__ wv, const float* __restrict__ wo,
    __half* __restrict__ x16, __half* __restrict__ q16,
    __half* __restrict__ wq16, __half* __restrict__ wk16,
    __half* __restrict__ wv16, __half* __restrict__ wo16)
{
    const int nX4 = MM * CC / 4;   // 2^20
    const int nW4 = CC * CC / 4;   // 2^18
    int i = (blockIdx.x * 256 + threadIdx.x) * 4;   // aligned 4-run, one segment
    const float* src; __half* dst;
    if (i < nX4)          { src = x;  dst = x16; }
    else if (i < 2 * nX4) { src = q;  dst = q16; i -= nX4; }
    else {
        int j = i - 2 * nX4;
        int w = j >> 18;
        i = j & (nW4 - 1);
        switch (w) {
            case 0:  src = wq; dst = wq16; break;
            case 1:  src = wk; dst = wk16; break;
            case 2:  src = wv; dst = wv16; break;
            default: src = wo; dst = wo16; break;
        }
    }
    float4 v0 = ((const float4*)src)[i];
    float4 v1 = ((const float4*)src)[i + 1];
    float4 v2 = ((const float4*)src)[i + 2];
    float4 v3 = ((const float4*)src)[i + 3];
    __half2* d = (__half2*)dst + 2 * i;
    d[0] = __floats2half2_rn(v0.x, v0.y); d[1] = __floats2half2_rn(v0.z, v0.w);
    d[2] = __floats2half2_rn(v1.x, v1.y); d[3] = __floats2half2_rn(v1.z, v1.w);
    d[4] = __floats2half2_rn(v2.x, v2.y); d[5] = __floats2half2_rn(v2.z, v2.w);
    d[6] = __floats2half2_rn(v3.x, v3.y); d[7] = __floats2half2_rn(v3.z, v3.w);
}

// ---------------------------------------------------------------------------
// GEMM body (R9 shape): Y[4096,1024] = (A @ W^T + bias) * oscale, fp16 pass.
// CTA 128x128, BK=64, 8 warps (warp 32x64), 3-stage pipeline (32KB/stage),
// one barrier per chunk, issue-BEFORE-compute reorder, 2 CTAs/SM by smem.
// ---------------------------------------------------------------------------
template<int OUT>
__device__ __forceinline__ void gemm_body(
    const __half* __restrict__ A, const __half* __restrict__ B,
    const float* __restrict__ bias, void* __restrict__ Y0,
    uint32_t sb, int bm, int bn, float oscale)
{
    constexpr int PART  = 16384;    // 128 rows x 64 halves (128 B/row)
    constexpr int STAGE = 2 * PART;

    const int t = threadIdx.x, lane = t & 31, wid = t >> 5;
    const int wm = wid & 3, wn = wid >> 2;
    const int lm = lane & 7;
    const int q1 = (lane >> 3) & 1, q2 = lane >> 4;

    float acc[2][8][4];
#pragma unroll
    for (int mf = 0; mf < 2; mf++)
#pragma unroll
        for (int nf = 0; nf < 8; nf++)
#pragma unroll
            for (int j = 0; j < 4; j++) acc[mf][nf][j] = 0.0f;

    auto issue = [&](int stg, int kt) {
        const int k0 = kt * 64;
#pragma unroll
        for (int p = 0; p < 2; p++) {
            uint32_t base = sb + stg * STAGE + p * PART;
            const __half* s = p ? B : A;
            const int rb = p ? bn : bm;
#pragma unroll
            for (int i = 0; i < 4; i++) {
                int c = t + 256 * i;
                uint32_t row = c >> 3, ch = c & 7;
                uint32_t dst = base + sw_row128(row, ch * 16);
                const void* g = s + (size_t)(rb + row) * CC + k0 + ch * 8;
                CP_ASYNC_16(dst, g);
            }
        }
    };

    // Hoisted ldsm addressing (row&7 == lm for every fragment this lane reads)
    const uint32_t swl = (uint32_t)lm << 4;
    uint32_t aR[2], bR[4], cw[4];
#pragma unroll
    for (int mf = 0; mf < 2; mf++)
        aR[mf] = (uint32_t)(wm * 32 + mf * 16 + q1 * 8 + lm) * 128u;
#pragma unroll
    for (int g = 0; g < 4; g++)
        bR[g] = (uint32_t)PART + (uint32_t)(wn * 64 + g * 16 + q1 * 8 + lm) * 128u;
#pragma unroll
    for (int ks = 0; ks < 4; ks++)
        cw[ks] = ((uint32_t)(ks * 2 + q2) * 16u) ^ swl;

    auto compute = [&](int stg) {
        const uint32_t Ab = sb + stg * STAGE;
#pragma unroll
        for (int ks = 0; ks < 4; ks++) {
            uint32_t ah[2][4], bh[4][4];
#pragma unroll
            for (int mf = 0; mf < 2; mf++)
                ldsm4(ah[mf], Ab + aR[mf] + cw[ks]);
#pragma unroll
            for (int g = 0; g < 4; g++)
                ldsm4(bh[g], Ab + bR[g] + cw[ks]);
#pragma unroll
            for (int mf = 0; mf < 2; mf++)
#pragma unroll
                for (int g = 0; g < 4; g++) {
                    mma16816(acc[mf][2 * g],     ah[mf], bh[g][0], bh[g][2]);
                    mma16816(acc[mf][2 * g + 1], ah[mf], bh[g][1], bh[g][3]);
                }
        }
    };

    issue(0, 0); CP_COMMIT();
    issue(1, 1); CP_COMMIT();
    for (int kt = 0; kt < 16; kt++) {
        if (kt == 15) CP_WAIT(0); else CP_WAIT(1);
        __syncthreads();
        // Issue BEFORE compute: ~2 compute-phases of load slack, no tail LSU clash.
        // Overwrites stage (kt-1)%3, whose readers finished before this barrier.
        if (kt + 2 < 16) { issue((kt + 2) % 3, kt + 2); CP_COMMIT(); }
        compute(kt % 3);
    }

    // Epilogue
#pragma unroll
    for (int mf = 0; mf < 2; mf++) {
        const int r0 = bm + wm * 32 + mf * 16 + (lane >> 2);
#pragma unroll
        for (int nf = 0; nf < 8; nf++) {
            const int col = bn + wn * 64 + nf * 8 + (lane & 3) * 2;
            const float b0 = bias[col], b1 = bias[col + 1];
            float y0 = (acc[mf][nf][0] + b0) * oscale, y1 = (acc[mf][nf][1] + b1) * oscale;
            float y2 = (acc[mf][nf][2] + b0) * oscale, y3 = (acc[mf][nf][3] + b1) * oscale;
            if (OUT == 0) {
                *(float2*)((float*)Y0 + (size_t)r0 * CC + col)       = make_float2(y0, y1);
                *(float2*)((float*)Y0 + (size_t)(r0 + 8) * CC + col) = make_float2(y2, y3);
            } else {
                *(__half2*)((__half*)Y0 + (size_t)r0 * CC + col)       = __floats2half2_rn(y0, y1);
                *(__half2*)((__half*)Y0 + (size_t)(r0 + 8) * CC + col) = __floats2half2_rn(y2, y3);
            }
        }
    }
}

// Fused Q/K/V projection: grid (8, 32, 3); z selects problem.
__global__ __launch_bounds__(256) void gemm_qkv(
    const __half* __restrict__ q16, const __half* __restrict__ x16,
    const __half* __restrict__ wq, const __half* __restrict__ wk,
    const __half* __restrict__ wv,
    const float* __restrict__ bq, const float* __restrict__ bk,
    const float* __restrict__ bv,
    __half* __restrict__ Yq, __half* __restrict__ Yk, __half* __restrict__ Yv)
{
    extern __shared__ char smraw[];
    const uint32_t sb = smem_u32(smraw);
    const __half* A; const __half* B; const float* bias; __half* Y;
    float oscale = 1.0f;
    switch (blockIdx.z) {
        case 0:  A = q16; B = wq; bias = bq; Y = Yq; oscale = SL2E; break;
        case 1:  A = x16; B = wk; bias = bk; Y = Yk; break;
        default: A = x16; B = wv; bias = bv; Y = Yv; break;
    }
    gemm_body<1>(A, B, bias, Y, sb, blockIdx.y * 128, blockIdx.x * 128, oscale);
}

// Output projection: grid (8, 32), fp32 out.
__global__ __launch_bounds__(256) void gemm_out(
    const __half* __restrict__ A, const __half* __restrict__ B,
    const float* __restrict__ bias, float* __restrict__ Y)
{
    extern __shared__ char smraw[];
    const uint32_t sb = smem_u32(smraw);
    gemm_body<0>(A, B, bias, Y, sb, blockIdx.y * 128, blockIdx.x * 128, 1.0f);
}

// ---------------------------------------------------------------------------
// Flash attention — deferred-PV schedule, issue-before-compute reorder.
// 4-stage K/V ring (64KB), one barrier per tile, Q a-frags from global.
// Grid (32, 16, 2), 128 threads.
// ---------------------------------------------------------------------------
__global__ __launch_bounds__(128) void flash_mma(
    const __half* __restrict__ Q, const __half* __restrict__ K,
    const __half* __restrict__ V, __half* __restrict__ AO)
{
    extern __shared__ char smraw[];
    const uint32_t sb = smem_u32(smraw);

    const int t = threadIdx.x, lane = t & 31, wid = t >> 5;
    const int qt = blockIdx.x, h = blockIdx.y, b = blockIdx.z;
    const int lm = lane & 7;
    const int q1 = (lane >> 3) & 1, q2 = lane >> 4;
    const size_t hcol = (size_t)h * 64;
    const size_t rowQ = (size_t)(b * NN + qt * 64);

    const __half* srcs[2] = {K, V};
    auto issue = [&](int stg, int kt) {
        uint32_t base0 = sb + stg * 16384;
#pragma unroll
        for (int p = 0; p < 2; p++) {
            uint32_t base = base0 + p * 8192;
            const __half* s = srcs[p];
#pragma unroll
            for (int i = 0; i < 4; i++) {
                int c = t + 128 * i;
                uint32_t row = c >> 3, ch = c & 7;
                uint32_t dst = base + sw_row128(row, ch * 16);
                const void* g = s + (size_t)(b * NN + kt * 64 + row) * CC + hcol + ch * 8;
                CP_ASYNC_16(dst, g);
            }
        }
    };
    issue(0, 0); CP_COMMIT();
    issue(1, 1); CP_COMMIT();

    // Q a-frags straight from global
    uint32_t aq[4][4];
    {
        const __half* qp = Q + (rowQ + wid * 16 + (lane >> 2)) * CC + hcol + (lane & 3) * 2;
#pragma unroll
        for (int ks = 0; ks < 4; ks++) {
            aq[ks][0] = *(const uint32_t*)(qp + ks * 16);
            aq[ks][1] = *(const uint32_t*)(qp + 8 * CC + ks * 16);
            aq[ks][2] = *(const uint32_t*)(qp + ks * 16 + 8);
            aq[ks][3] = *(const uint32_t*)(qp + 8 * CC + ks * 16 + 8);
        }
    }

    // Hoisted ldsm addressing (row&7 == lm everywhere)
    const uint32_t swl = (uint32_t)lm << 4;
    uint32_t kR[4], vR[4], cw[4], cv[4];
#pragma unroll
    for (int g = 0; g < 4; g++)
        kR[g] = (uint32_t)(g * 16 + q1 * 8 + lm) * 128u;
#pragma unroll
    for (int ks = 0; ks < 4; ks++)
        vR[ks] = 8192u + (uint32_t)(ks * 16 + q1 * 8 + lm) * 128u;
#pragma unroll
    for (int ks = 0; ks < 4; ks++)
        cw[ks] = ((uint32_t)(ks * 2 + q2) * 16u) ^ swl;
#pragma unroll
    for (int g = 0; g < 4; g++)
        cv[g] = ((uint32_t)(g * 2 + q2) * 16u) ^ swl;

    float o[8][4];
#pragma unroll
    for (int nf = 0; nf < 8; nf++)
#pragma unroll
        for (int j = 0; j < 4; j++) o[nf][j] = 0.0f;
    float lsum[4] = {0.0f, 0.0f, 0.0f, 0.0f};
    const uint32_t ONES2 = 0x3C003C00u;

    uint32_t apA[4][4], apB[4][4];
    uint32_t prevKb = 0;

    auto iter = [&](int kt, uint32_t (*apW)[4], uint32_t (*apR)[4], bool doPV) {
        const int cur = kt & 3;
        if (kt == 31) CP_WAIT(0); else CP_WAIT(1);
        __syncthreads();
        // Issue before compute (overwrites stage kt-2: two barriers stale)
        if (kt + 2 < 32) { issue((kt + 2) & 3, kt + 2); CP_COMMIT(); }
        const uint32_t Kb = sb + cur * 16384;

        // S = Q @ K^T
        float s[8][4];
#pragma unroll
        for (int nf = 0; nf < 8; nf++)
#pragma unroll
            for (int j = 0; j < 4; j++) s[nf][j] = 0.0f;
#pragma unroll
        for (int ks = 0; ks < 4; ks++) {
            uint32_t bk[4][4];
#pragma unroll
            for (int g = 0; g < 4; g++)
                ldsm4(bk[g], Kb + kR[g] + cw[ks]);
#pragma unroll
            for (int g = 0; g < 4; g++) {
                mma16816(s[2 * g],     aq[ks], bk[g][0], bk[g][2]);
                mma16816(s[2 * g + 1], aq[ks], bk[g][1], bk[g][3]);
            }
        }

        // Deferred PV(t-1)
        if (doPV) {
#pragma unroll
            for (int ks = 0; ks < 4; ks++) {
                uint32_t bv[4][4];
#pragma unroll
                for (int g = 0; g < 4; g++)
                    ldsm4t(bv[g], prevKb + vR[ks] + cv[g]);
#pragma unroll
                for (int g = 0; g < 4; g++) {
                    mma16816(o[2 * g],     apR[ks], bv[g][0], bv[g][1]);
                    mma16816(o[2 * g + 1], apR[ks], bv[g][2], bv[g][3]);
                }
            }
        }

        // softmax(t)
#pragma unroll
        for (int tt = 0; tt < 4; tt++) {
            apW[tt][0] = h2ex2(pkh2(s[2 * tt][0],     s[2 * tt][1]));
            apW[tt][1] = h2ex2(pkh2(s[2 * tt][2],     s[2 * tt][3]));
            apW[tt][2] = h2ex2(pkh2(s[2 * tt + 1][0], s[2 * tt + 1][1]));
            apW[tt][3] = h2ex2(pkh2(s[2 * tt + 1][2], s[2 * tt + 1][3]));
        }
#pragma unroll
        for (int ks = 0; ks < 4; ks++)
            mma16816(lsum, apW[ks], ONES2, ONES2);

        prevKb = Kb;
    };

    iter(0, apA, apB, false);
    iter(1, apB, apA, true);
    for (int kt2 = 1; kt2 < 16; kt2++) {
        iter(2 * kt2,     apA, apB, true);
        iter(2 * kt2 + 1, apB, apA, true);
    }
    // Final PV for tile 31
#pragma unroll
    for (int ks = 0; ks < 4; ks++) {
        uint32_t bv[4][4];
#pragma unroll
        for (int g = 0; g < 4; g++)
            ldsm4t(bv[g], prevKb + vR[ks] + cv[g]);
#pragma unroll
        for (int g = 0; g < 4; g++) {
            mma16816(o[2 * g],     apB[ks], bv[g][0], bv[g][1]);
            mma16816(o[2 * g + 1], apB[ks], bv[g][2], bv[g][3]);
        }
    }

    // Epilogue: normalize, emit fp16
    const float i0 = 1.0f / lsum[0], i1 = 1.0f / lsum[2];
    const size_t ro = (rowQ + wid * 16 + (lane >> 2)) * CC + hcol;
#pragma unroll
    for (int nf = 0; nf < 8; nf++) {
        const int col = nf * 8 + (lane & 3) * 2;
        *(__half2*)&AO[ro + col]          = __floats2half2_rn(o[nf][0] * i0, o[nf][1] * i0);
        *(__half2*)&AO[ro + 8 * CC + col] = __floats2half2_rn(o[nf][2] * i1, o[nf][3] * i1);
    }
}

// ---------------------------------------------------------------------------
extern "C" void kernel_launch(void* const* d_in, const int* in_sizes, int n_in,
                              void* d_out, int out_size)
{
    const float* x       = (const float*)d_in[0];
    const float* queries = (const float*)d_in[1];
    const float* wq = (const float*)d_in[2];
    const float* bq = (const float*)d_in[3];
    const float* wk = (const float*)d_in[4];
    const float* bk = (const float*)d_in[5];
    const float* wv = (const float*)d_in[6];
    const float* bv = (const float*)d_in[7];
    const float* wo = (const float*)d_in[8];
    const float* bo = (const float*)d_in[9];
    float* out = (float*)d_out;

    __half *q16, *x16, *wq16, *wk16, *wv16, *wo16, *ao16, *Qp, *Kp, *Vp;
    cudaGetSymbolAddress((void**)&q16,  g_q16);
    cudaGetSymbolAddress((void**)&x16,  g_x16);
    cudaGetSymbolAddress((void**)&wq16, g_wq16);
    cudaGetSymbolAddress((void**)&wk16, g_wk16);
    cudaGetSymbolAddress((void**)&wv16, g_wv16);
    cudaGetSymbolAddress((void**)&wo16, g_wo16);
    cudaGetSymbolAddress((void**)&ao16, g_ao16);
    cudaGetSymbolAddress((void**)&Qp,   g_Qp);
    cudaGetSymbolAddress((void**)&Kp,   g_Kp);
    cudaGetSymbolAddress((void**)&Vp,   g_V16);

    const int gsmem = 3 * 32768;   // 98304
    cudaFuncSetAttribute(gemm_qkv, cudaFuncAttributeMaxDynamicSharedMemorySize, gsmem);
    cudaFuncSetAttribute(gemm_out, cudaFuncAttributeMaxDynamicSharedMemorySize, gsmem);
    cudaFuncSetAttribute(flash_mma, cudaFuncAttributeMaxDynamicSharedMemorySize, 65536);

    const int nX4 = MM * CC / 4;   // 1M
    const int nW4 = CC * CC / 4;   // 256K
    cvt_all_k<<<(2 * nX4 + 4 * nW4) / 1024, 256>>>(
        x, queries, wq, wk, wv, wo, x16, q16, wq16, wk16, wv16, wo16);

    gemm_qkv<<<dim3(8, 32, 3), 256, gsmem>>>(q16, x16, wq16, wk16, wv16,
                                             bq, bk, bv, Qp, Kp, Vp);

    flash_mma<<<dim3(NN / 64, HH, BB), 128, 65536>>>(Qp, Kp, Vp, ao16);

    gemm_out<<<dim3(8, 32), 256, gsmem>>>(ao16, wo16, bo, out);
}

// round 13
// speedup vs baseline: 1.0111x; 1.0111x over previous
#include <cuda_runtime.h>
#include <cuda_fp16.h>
#include <cstdint>

// Problem constants
#define BB 2
#define NN 2048
#define CC 1024
#define HH 16
#define MM (BB * NN)            // 4096 rows
#define SL2E 0.04506933791622f  // (1/32) * log2(e)

// ---------------------------------------------------------------------------
// Scratch (device globals; no allocation allowed)
// ---------------------------------------------------------------------------
__device__ __half g_q16[MM * CC];                 // queries fp16
__device__ __half g_x16[MM * CC];                 // x fp16
__device__ __half g_wq16[CC * CC], g_wk16[CC * CC], g_wv16[CC * CC], g_wo16[CC * CC];
__device__ __half g_ao16[MM * CC];                // attention out fp16
__device__ __half g_Qp[MM * CC], g_Kp[MM * CC];   // projected Q (pre-scaled), K
__device__ __half g_V16[MM * CC];                 // projected V (fp16)

// ---------------------------------------------------------------------------
// Helpers (portable PTX only: mma.sync / ldmatrix / cp.async)
// ---------------------------------------------------------------------------
__device__ __forceinline__ uint32_t smem_u32(const void* p) {
    uint32_t a;
    asm("{ .reg .u64 t; cvta.to.shared.u64 t, %1; cvt.u32.u64 %0, t; }"
        : "=r"(a) : "l"(p));
    return a;
}

#define CP_ASYNC_16(dst, src) \
    asm volatile("cp.async.cg.shared.global [%0], [%1], 16;" :: "r"(dst), "l"(src))
#define CP_COMMIT() asm volatile("cp.async.commit_group;" ::: "memory")
#define CP_WAIT(n)  asm volatile("cp.async.wait_group %0;" :: "n"(n) : "memory")

__device__ __forceinline__ void ldsm4(uint32_t* r, uint32_t a) {
    asm volatile("ldmatrix.sync.aligned.m8n8.x4.shared.b16 {%0,%1,%2,%3}, [%4];"
        : "=r"(r[0]), "=r"(r[1]), "=r"(r[2]), "=r"(r[3]) : "r"(a));
}
__device__ __forceinline__ void ldsm4t(uint32_t* r, uint32_t a) {
    asm volatile("ldmatrix.sync.aligned.m8n8.x4.trans.shared.b16 {%0,%1,%2,%3}, [%4];"
        : "=r"(r[0]), "=r"(r[1]), "=r"(r[2]), "=r"(r[3]) : "r"(a));
}

__device__ __forceinline__ void mma16816(float* c, const uint32_t* a,
                                         uint32_t b0, uint32_t b1) {
    asm volatile(
        "mma.sync.aligned.m16n8k16.row.col.f32.f16.f16.f32 "
        "{%0,%1,%2,%3}, {%4,%5,%6,%7}, {%8,%9}, {%0,%1,%2,%3};"
        : "+f"(c[0]), "+f"(c[1]), "+f"(c[2]), "+f"(c[3])
        : "r"(a[0]), "r"(a[1]), "r"(a[2]), "r"(a[3]), "r"(b0), "r"(b1));
}

__device__ __forceinline__ uint32_t pkh2(float a, float b) {
    __half2 h = __floats2half2_rn(a, b);
    return *reinterpret_cast<uint32_t*>(&h);
}

// exp2 on a packed half2 pair (one MUFU op for two values)
__device__ __forceinline__ uint32_t h2ex2(uint32_t x) {
    uint32_t y;
    asm("ex2.approx.f16x2 %0, %1;" : "=r"(y) : "r"(x));
    return y;
}

// SW128 for 128-byte rows: SW128(row*128 + c) = row*128 + (c ^ ((row&7)<<4))
__device__ __forceinline__ uint32_t sw_row128(uint32_t row, uint32_t cbytes) {
    return row * 128u + (cbytes ^ ((row & 7u) << 4));
}

// ---------------------------------------------------------------------------
// fp32 -> fp16 conversion: ALL tensors, 4 float4 per thread (MLP=4).
// Segments (float4 units): [0,1M) x | [1M,2M) q | [2M,3M) wq,wk,wv,wo.
// ---------------------------------------------------------------------------
__global__ __launch_bounds__(256) void cvt_all_k(
    const float* __restrict__ x, const float* __restrict__ q,
    const float* __restrict__ wq, const float* __restrict__ wk,
    const float* __restrict__ wv, const float* __restrict__ wo,
    __half* __restrict__ x16, __half* __restrict__ q16,
    __half* __restrict__ wq16, __half* __restrict__ wk16,
    __half* __restrict__ wv16, __half* __restrict__ wo16)
{
    const int nX4 = MM * CC / 4;   // 2^20
    const int nW4 = CC * CC / 4;   // 2^18
    int i = (blockIdx.x * 256 + threadIdx.x) * 4;   // aligned 4-run, one segment
    const float* src; __half* dst;
    if (i < nX4)          { src = x;  dst = x16; }
    else if (i < 2 * nX4) { src = q;  dst = q16; i -= nX4; }
    else {
        int j = i - 2 * nX4;
        int w = j >> 18;
        i = j & (nW4 - 1);
        switch (w) {
            case 0:  src = wq; dst = wq16; break;
            case 1:  src = wk; dst = wk16; break;
            case 2:  src = wv; dst = wv16; break;
            default: src = wo; dst = wo16; break;
        }
    }
    float4 v0 = ((const float4*)src)[i];
    float4 v1 = ((const float4*)src)[i + 1];
    float4 v2 = ((const float4*)src)[i + 2];
    float4 v3 = ((const float4*)src)[i + 3];
    __half2* d = (__half2*)dst + 2 * i;
    d[0] = __floats2half2_rn(v0.x, v0.y); d[1] = __floats2half2_rn(v0.z, v0.w);
    d[2] = __floats2half2_rn(v1.x, v1.y); d[3] = __floats2half2_rn(v1.z, v1.w);
    d[4] = __floats2half2_rn(v2.x, v2.y); d[5] = __floats2half2_rn(v2.z, v2.w);
    d[6] = __floats2half2_rn(v3.x, v3.y); d[7] = __floats2half2_rn(v3.z, v3.w);
}

// ---------------------------------------------------------------------------
// GEMM body (R9 structure): Y[4096,1024] = (A @ W^T + bias)*oscale, fp16 pass.
// CTA 128x128, BK=64 (128B rows, SW128), 8 warps (32x64), 3-stage pipeline,
// ONE barrier per chunk; compute FIRST, prefetch AFTER (LSU ordering!).
// ---------------------------------------------------------------------------
template<int OUT>
__device__ __forceinline__ void gemm_body(
    const __half* __restrict__ A, const __half* __restrict__ B,
    const float* __restrict__ bias, void* __restrict__ Y0,
    uint32_t sb, int bm, int bn, float oscale)
{
    constexpr int PART  = 16384;    // 128 rows x 64 halves (128 B/row)
    constexpr int STAGE = 2 * PART;

    const int t = threadIdx.x, lane = t & 31, wid = t >> 5;
    const int wm = wid & 3, wn = wid >> 2;
    const int lm = lane & 7;
    const int q1 = (lane >> 3) & 1, q2 = lane >> 4;

    float acc[2][8][4];
#pragma unroll
    for (int mf = 0; mf < 2; mf++)
#pragma unroll
        for (int nf = 0; nf < 8; nf++)
#pragma unroll
            for (int j = 0; j < 4; j++) acc[mf][nf][j] = 0.0f;

    auto issue = [&](int stg, int kt) {
        const int k0 = kt * 64;
#pragma unroll
        for (int p = 0; p < 2; p++) {
            uint32_t base = sb + stg * STAGE + p * PART;
            const __half* s = p ? B : A;
            const int rb = p ? bn : bm;
#pragma unroll
            for (int i = 0; i < 4; i++) {
                int c = t + 256 * i;
                uint32_t row = c >> 3, ch = c & 7;
                uint32_t dst = base + sw_row128(row, ch * 16);
                const void* g = s + (size_t)(rb + row) * CC + k0 + ch * 8;
                CP_ASYNC_16(dst, g);
            }
        }
    };

    // Hoisted ldsm addressing (row&7 == lm for every fragment this lane reads)
    const uint32_t swl = (uint32_t)lm << 4;
    uint32_t aR[2], bR[4], cw[4];
#pragma unroll
    for (int mf = 0; mf < 2; mf++)
        aR[mf] = (uint32_t)(wm * 32 + mf * 16 + q1 * 8 + lm) * 128u;
#pragma unroll
    for (int g = 0; g < 4; g++)
        bR[g] = (uint32_t)PART + (uint32_t)(wn * 64 + g * 16 + q1 * 8 + lm) * 128u;
#pragma unroll
    for (int ks = 0; ks < 4; ks++)
        cw[ks] = ((uint32_t)(ks * 2 + q2) * 16u) ^ swl;

    auto compute = [&](int stg) {
        const uint32_t Ab = sb + stg * STAGE;
#pragma unroll
        for (int ks = 0; ks < 4; ks++) {
            uint32_t ah[2][4], bh[4][4];
#pragma unroll
            for (int mf = 0; mf < 2; mf++)
                ldsm4(ah[mf], Ab + aR[mf] + cw[ks]);
#pragma unroll
            for (int g = 0; g < 4; g++)
                ldsm4(bh[g], Ab + bR[g] + cw[ks]);
#pragma unroll
            for (int mf = 0; mf < 2; mf++)
#pragma unroll
                for (int g = 0; g < 4; g++) {
                    mma16816(acc[mf][2 * g],     ah[mf], bh[g][0], bh[g][2]);
                    mma16816(acc[mf][2 * g + 1], ah[mf], bh[g][1], bh[g][3]);
                }
        }
    };

    issue(0, 0); CP_COMMIT();
    issue(1, 1); CP_COMMIT();
    for (int kt = 0; kt < 16; kt++) {
        if (kt == 15) CP_WAIT(0); else CP_WAIT(1);
        __syncthreads();
        compute(kt % 3);
        if (kt + 2 < 16) { issue((kt + 2) % 3, kt + 2); CP_COMMIT(); }
    }

    // Epilogue
#pragma unroll
    for (int mf = 0; mf < 2; mf++) {
        const int r0 = bm + wm * 32 + mf * 16 + (lane >> 2);
#pragma unroll
        for (int nf = 0; nf < 8; nf++) {
            const int col = bn + wn * 64 + nf * 8 + (lane & 3) * 2;
            const float b0 = bias[col], b1 = bias[col + 1];
            float y0 = (acc[mf][nf][0] + b0) * oscale, y1 = (acc[mf][nf][1] + b1) * oscale;
            float y2 = (acc[mf][nf][2] + b0) * oscale, y3 = (acc[mf][nf][3] + b1) * oscale;
            if (OUT == 0) {
                *(float2*)((float*)Y0 + (size_t)r0 * CC + col)       = make_float2(y0, y1);
                *(float2*)((float*)Y0 + (size_t)(r0 + 8) * CC + col) = make_float2(y2, y3);
            } else {
                *(__half2*)((__half*)Y0 + (size_t)r0 * CC + col)       = __floats2half2_rn(y0, y1);
                *(__half2*)((__half*)Y0 + (size_t)(r0 + 8) * CC + col) = __floats2half2_rn(y2, y3);
            }
        }
    }
}

// Fused Q/K/V projection: grid (8, 32, 3); z selects problem.
__global__ __launch_bounds__(256) void gemm_qkv(
    const __half* __restrict__ q16, const __half* __restrict__ x16,
    const __half* __restrict__ wq, const __half* __restrict__ wk,
    const __half* __restrict__ wv,
    const float* __restrict__ bq, const float* __restrict__ bk,
    const float* __restrict__ bv,
    __half* __restrict__ Yq, __half* __restrict__ Yk, __half* __restrict__ Yv)
{
    extern __shared__ char smraw[];
    const uint32_t sb = smem_u32(smraw);
    const __half* A; const __half* B; const float* bias; __half* Y;
    float oscale = 1.0f;
    switch (blockIdx.z) {
        case 0:  A = q16; B = wq; bias = bq; Y = Yq; oscale = SL2E; break;
        case 1:  A = x16; B = wk; bias = bk; Y = Yk; break;
        default: A = x16; B = wv; bias = bv; Y = Yv; break;
    }
    gemm_body<1>(A, B, bias, Y, sb, blockIdx.y * 128, blockIdx.x * 128, oscale);
}

// Output projection: grid (8, 32), fp32 out.
__global__ __launch_bounds__(256) void gemm_out(
    const __half* __restrict__ A, const __half* __restrict__ B,
    const float* __restrict__ bias, float* __restrict__ Y)
{
    extern __shared__ char smraw[];
    const uint32_t sb = smem_u32(smraw);
    gemm_body<0>(A, B, bias, Y, sb, blockIdx.y * 128, blockIdx.x * 128, 1.0f);
}

// ---------------------------------------------------------------------------
// Flash attention (R9 structure) — deferred-PV schedule: per iter QK(t),
// PV(t-1), softmax(t); prefetch issued at END of iter (after ldsm drains).
// 4-stage K/V ring (64KB), one barrier per tile, Q a-frags from global.
// Grid (32, 16, 2), 128 threads.
// ---------------------------------------------------------------------------
__global__ __launch_bounds__(128) void flash_mma(
    const __half* __restrict__ Q, const __half* __restrict__ K,
    const __half* __restrict__ V, __half* __restrict__ AO)
{
    extern __shared__ char smraw[];
    const uint32_t sb = smem_u32(smraw);

    const int t = threadIdx.x, lane = t & 31, wid = t >> 5;
    const int qt = blockIdx.x, h = blockIdx.y, b = blockIdx.z;
    const int lm = lane & 7;
    const int q1 = (lane >> 3) & 1, q2 = lane >> 4;
    const size_t hcol = (size_t)h * 64;
    const size_t rowQ = (size_t)(b * NN + qt * 64);

    const __half* srcs[2] = {K, V};
    auto issue = [&](int stg, int kt) {
        uint32_t base0 = sb + stg * 16384;
#pragma unroll
        for (int p = 0; p < 2; p++) {
            uint32_t base = base0 + p * 8192;
            const __half* s = srcs[p];
#pragma unroll
            for (int i = 0; i < 4; i++) {
                int c = t + 128 * i;
                uint32_t row = c >> 3, ch = c & 7;
                uint32_t dst = base + sw_row128(row, ch * 16);
                const void* g = s + (size_t)(b * NN + kt * 64 + row) * CC + hcol + ch * 8;
                CP_ASYNC_16(dst, g);
            }
        }
    };
    issue(0, 0); CP_COMMIT();
    issue(1, 1); CP_COMMIT();

    // Q a-frags straight from global
    uint32_t aq[4][4];
    {
        const __half* qp = Q + (rowQ + wid * 16 + (lane >> 2)) * CC + hcol + (lane & 3) * 2;
#pragma unroll
        for (int ks = 0; ks < 4; ks++) {
            aq[ks][0] = *(const uint32_t*)(qp + ks * 16);
            aq[ks][1] = *(const uint32_t*)(qp + 8 * CC + ks * 16);
            aq[ks][2] = *(const uint32_t*)(qp + ks * 16 + 8);
            aq[ks][3] = *(const uint32_t*)(qp + 8 * CC + ks * 16 + 8);
        }
    }

    // Hoisted ldsm addressing (row&7 == lm everywhere)
    const uint32_t swl = (uint32_t)lm << 4;
    uint32_t kR[4], vR[4], cw[4], cv[4];
#pragma unroll
    for (int g = 0; g < 4; g++)
        kR[g] = (uint32_t)(g * 16 + q1 * 8 + lm) * 128u;
#pragma unroll
    for (int ks = 0; ks < 4; ks++)
        vR[ks] = 8192u + (uint32_t)(ks * 16 + q1 * 8 + lm) * 128u;
#pragma unroll
    for (int ks = 0; ks < 4; ks++)
        cw[ks] = ((uint32_t)(ks * 2 + q2) * 16u) ^ swl;
#pragma unroll
    for (int g = 0; g < 4; g++)
        cv[g] = ((uint32_t)(g * 2 + q2) * 16u) ^ swl;

    float o[8][4];
#pragma unroll
    for (int nf = 0; nf < 8; nf++)
#pragma unroll
        for (int j = 0; j < 4; j++) o[nf][j] = 0.0f;
    float lsum[4] = {0.0f, 0.0f, 0.0f, 0.0f};
    const uint32_t ONES2 = 0x3C003C00u;

    uint32_t apA[4][4], apB[4][4];
    uint32_t prevKb = 0;

    auto iter = [&](int kt, uint32_t (*apW)[4], uint32_t (*apR)[4], bool doPV) {
        const int cur = kt & 3;
        if (kt == 31) CP_WAIT(0); else CP_WAIT(1);
        __syncthreads();
        const uint32_t Kb = sb + cur * 16384;

        // S = Q @ K^T
        float s[8][4];
#pragma unroll
        for (int nf = 0; nf < 8; nf++)
#pragma unroll
            for (int j = 0; j < 4; j++) s[nf][j] = 0.0f;
#pragma unroll
        for (int ks = 0; ks < 4; ks++) {
            uint32_t bk[4][4];
#pragma unroll
            for (int g = 0; g < 4; g++)
                ldsm4(bk[g], Kb + kR[g] + cw[ks]);
#pragma unroll
            for (int g = 0; g < 4; g++) {
                mma16816(s[2 * g],     aq[ks], bk[g][0], bk[g][2]);
                mma16816(s[2 * g + 1], aq[ks], bk[g][1], bk[g][3]);
            }
        }

        // Deferred PV(t-1)
        if (doPV) {
#pragma unroll
            for (int ks = 0; ks < 4; ks++) {
                uint32_t bv[4][4];
#pragma unroll
                for (int g = 0; g < 4; g++)
                    ldsm4t(bv[g], prevKb + vR[ks] + cv[g]);
#pragma unroll
                for (int g = 0; g < 4; g++) {
                    mma16816(o[2 * g],     apR[ks], bv[g][0], bv[g][1]);
                    mma16816(o[2 * g + 1], apR[ks], bv[g][2], bv[g][3]);
                }
            }
        }

        // softmax(t)
#pragma unroll
        for (int tt = 0; tt < 4; tt++) {
            apW[tt][0] = h2ex2(pkh2(s[2 * tt][0],     s[2 * tt][1]));
            apW[tt][1] = h2ex2(pkh2(s[2 * tt][2],     s[2 * tt][3]));
            apW[tt][2] = h2ex2(pkh2(s[2 * tt + 1][0], s[2 * tt + 1][1]));
            apW[tt][3] = h2ex2(pkh2(s[2 * tt + 1][2], s[2 * tt + 1][3]));
        }
#pragma unroll
        for (int ks = 0; ks < 4; ks++)
            mma16816(lsum, apW[ks], ONES2, ONES2);

        prevKb = Kb;
        if (kt + 2 < 32) { issue((kt + 2) & 3, kt + 2); CP_COMMIT(); }
    };

    iter(0, apA, apB, false);
    iter(1, apB, apA, true);
    for (int kt2 = 1; kt2 < 16; kt2++) {
        iter(2 * kt2,     apA, apB, true);
        iter(2 * kt2 + 1, apB, apA, true);
    }
    // Final PV for tile 31
#pragma unroll
    for (int ks = 0; ks < 4; ks++) {
        uint32_t bv[4][4];
#pragma unroll
        for (int g = 0; g < 4; g++)
            ldsm4t(bv[g], prevKb + vR[ks] + cv[g]);
#pragma unroll
        for (int g = 0; g < 4; g++) {
            mma16816(o[2 * g],     apB[ks], bv[g][0], bv[g][1]);
            mma16816(o[2 * g + 1], apB[ks], bv[g][2], bv[g][3]);
        }
    }

    // Epilogue: normalize, emit fp16
    const float i0 = 1.0f / lsum[0], i1 = 1.0f / lsum[2];
    const size_t ro = (rowQ + wid * 16 + (lane >> 2)) * CC + hcol;
#pragma unroll
    for (int nf = 0; nf < 8; nf++) {
        const int col = nf * 8 + (lane & 3) * 2;
        *(__half2*)&AO[ro + col]          = __floats2half2_rn(o[nf][0] * i0, o[nf][1] * i0);
        *(__half2*)&AO[ro + 8 * CC + col] = __floats2half2_rn(o[nf][2] * i1, o[nf][3] * i1);
    }
}

// ---------------------------------------------------------------------------
extern "C" void kernel_launch(void* const* d_in, const int* in_sizes, int n_in,
                              void* d_out, int out_size)
{
    const float* x       = (const float*)d_in[0];
    const float* queries = (const float*)d_in[1];
    const float* wq = (const float*)d_in[2];
    const float* bq = (const float*)d_in[3];
    const float* wk = (const float*)d_in[4];
    const float* bk = (const float*)d_in[5];
    const float* wv = (const float*)d_in[6];
    const float* bv = (const float*)d_in[7];
    const float* wo = (const float*)d_in[8];
    const float* bo = (const float*)d_in[9];
    float* out = (float*)d_out;

    __half *q16, *x16, *wq16, *wk16, *wv16, *wo16, *ao16, *Qp, *Kp, *Vp;
    cudaGetSymbolAddress((void**)&q16,  g_q16);
    cudaGetSymbolAddress((void**)&x16,  g_x16);
    cudaGetSymbolAddress((void**)&wq16, g_wq16);
    cudaGetSymbolAddress((void**)&wk16, g_wk16);
    cudaGetSymbolAddress((void**)&wv16, g_wv16);
    cudaGetSymbolAddress((void**)&wo16, g_wo16);
    cudaGetSymbolAddress((void**)&ao16, g_ao16);
    cudaGetSymbolAddress((void**)&Qp,   g_Qp);
    cudaGetSymbolAddress((void**)&Kp,   g_Kp);
    cudaGetSymbolAddress((void**)&Vp,   g_V16);

    const int gsmem = 3 * 32768;   // 98304
    cudaFuncSetAttribute(gemm_qkv, cudaFuncAttributeMaxDynamicSharedMemorySize, gsmem);
    cudaFuncSetAttribute(gemm_out, cudaFuncAttributeMaxDynamicSharedMemorySize, gsmem);
    cudaFuncSetAttribute(flash_mma, cudaFuncAttributeMaxDynamicSharedMemorySize, 65536);

    const int nX4 = MM * CC / 4;   // 1M
    const int nW4 = CC * CC / 4;   // 256K
    cvt_all_k<<<(2 * nX4 + 4 * nW4) / 1024, 256>>>(
        x, queries, wq, wk, wv, wo, x16, q16, wq16, wk16, wv16, wo16);

    gemm_qkv<<<dim3(8, 32, 3), 256, gsmem>>>(q16, x16, wq16, wk16, wv16,
                                             bq, bk, bv, Qp, Kp, Vp);

    flash_mma<<<dim3(NN / 64, HH, BB), 128, 65536>>>(Qp, Kp, Vp, ao16);

    gemm_out<<<dim3(8, 32), 256, gsmem>>>(ao16, wo16, bo, out);
}

// round 14
// speedup vs baseline: 1.0866x; 1.0746x over previous
#include <cuda_runtime.h>
#include <cuda_fp16.h>
#include <cstdint>

// Problem constants
#define BB 2
#define NN 2048
#define CC 1024
#define HH 16
#define MM (BB * NN)            // 4096 rows
#define SL2E 0.04506933791622f  // (1/32) * log2(e)

// ---------------------------------------------------------------------------
// Scratch (device globals; no allocation allowed)
// ---------------------------------------------------------------------------
__device__ __half g_q16[MM * CC];                 // queries fp16
__device__ __half g_x16[MM * CC];                 // x fp16
__device__ __half g_wq16[CC * CC], g_wk16[CC * CC], g_wv16[CC * CC], g_wo16[CC * CC];
__device__ __half g_ao16[MM * CC];                // attention out fp16
__device__ __half g_Qp[MM * CC], g_Kp[MM * CC];   // projected Q (pre-scaled), K
__device__ __half g_V16[MM * CC];                 // projected V (fp16)

// ---------------------------------------------------------------------------
// Helpers (portable PTX only: mma.sync / ldmatrix / cp.async)
// ---------------------------------------------------------------------------
__device__ __forceinline__ uint32_t smem_u32(const void* p) {
    uint32_t a;
    asm("{ .reg .u64 t; cvta.to.shared.u64 t, %1; cvt.u32.u64 %0, t; }"
        : "=r"(a) : "l"(p));
    return a;
}

#define CP_ASYNC_16(dst, src) \
    asm volatile("cp.async.cg.shared.global [%0], [%1], 16;" :: "r"(dst), "l"(src))
#define CP_COMMIT() asm volatile("cp.async.commit_group;" ::: "memory")
#define CP_WAIT(n)  asm volatile("cp.async.wait_group %0;" :: "n"(n) : "memory")

__device__ __forceinline__ void ldsm4(uint32_t* r, uint32_t a) {
    asm volatile("ldmatrix.sync.aligned.m8n8.x4.shared.b16 {%0,%1,%2,%3}, [%4];"
        : "=r"(r[0]), "=r"(r[1]), "=r"(r[2]), "=r"(r[3]) : "r"(a));
}
__device__ __forceinline__ void ldsm4t(uint32_t* r, uint32_t a) {
    asm volatile("ldmatrix.sync.aligned.m8n8.x4.trans.shared.b16 {%0,%1,%2,%3}, [%4];"
        : "=r"(r[0]), "=r"(r[1]), "=r"(r[2]), "=r"(r[3]) : "r"(a));
}

__device__ __forceinline__ void mma16816(float* c, const uint32_t* a,
                                         uint32_t b0, uint32_t b1) {
    asm volatile(
        "mma.sync.aligned.m16n8k16.row.col.f32.f16.f16.f32 "
        "{%0,%1,%2,%3}, {%4,%5,%6,%7}, {%8,%9}, {%0,%1,%2,%3};"
        : "+f"(c[0]), "+f"(c[1]), "+f"(c[2]), "+f"(c[3])
        : "r"(a[0]), "r"(a[1]), "r"(a[2]), "r"(a[3]), "r"(b0), "r"(b1));
}

__device__ __forceinline__ uint32_t pkh2(float a, float b) {
    __half2 h = __floats2half2_rn(a, b);
    return *reinterpret_cast<uint32_t*>(&h);
}

// exp2 on a packed half2 pair (one MUFU op for two values)
__device__ __forceinline__ uint32_t h2ex2(uint32_t x) {
    uint32_t y;
    asm("ex2.approx.f16x2 %0, %1;" : "=r"(y) : "r"(x));
    return y;
}

// SW128 for 128-byte rows: SW128(row*128 + c) = row*128 + (c ^ ((row&7)<<4))
__device__ __forceinline__ uint32_t sw_row128(uint32_t row, uint32_t cbytes) {
    return row * 128u + (cbytes ^ ((row & 7u) << 4));
}

// ---------------------------------------------------------------------------
// fp32 -> fp16 conversion: ALL tensors, one launch.
// Each CTA owns a 1024-float4 chunk; thread t handles t, t+256, t+512, t+768
// (coalesced 512B/warp loads, coalesced 8B stores, 4 LDGs in flight).
// Segment sizes are multiples of 1024 f4, so chunks never straddle segments.
// ---------------------------------------------------------------------------
__global__ __launch_bounds__(256) void cvt_all_k(
    const float* __restrict__ x, const float* __restrict__ q,
    const float* __restrict__ wq, const float* __restrict__ wk,
    const float* __restrict__ wv, const float* __restrict__ wo,
    __half* __restrict__ x16, __half* __restrict__ q16,
    __half* __restrict__ wq16, __half* __restrict__ wk16,
    __half* __restrict__ wv16, __half* __restrict__ wo16)
{
    const int nX4 = MM * CC / 4;   // 2^20
    const int nW4 = CC * CC / 4;   // 2^18
    int base = blockIdx.x * 1024;  // chunk start (float4 units)
    const float* src; __half* dst;
    if (base < nX4)          { src = x;  dst = x16; }
    else if (base < 2 * nX4) { src = q;  dst = q16; base -= nX4; }
    else {
        int j = base - 2 * nX4;
        int w = j >> 18;
        base = j & (nW4 - 1);
        switch (w) {
            case 0:  src = wq; dst = wq16; break;
            case 1:  src = wk; dst = wk16; break;
            case 2:  src = wv; dst = wv16; break;
            default: src = wo; dst = wo16; break;
        }
    }
    const int i0 = base + threadIdx.x;
    float4 v0 = ((const float4*)src)[i0];
    float4 v1 = ((const float4*)src)[i0 + 256];
    float4 v2 = ((const float4*)src)[i0 + 512];
    float4 v3 = ((const float4*)src)[i0 + 768];
    uint2* d = (uint2*)dst;
    d[i0]       = make_uint2(pkh2(v0.x, v0.y), pkh2(v0.z, v0.w));
    d[i0 + 256] = make_uint2(pkh2(v1.x, v1.y), pkh2(v1.z, v1.w));
    d[i0 + 512] = make_uint2(pkh2(v2.x, v2.y), pkh2(v2.z, v2.w));
    d[i0 + 768] = make_uint2(pkh2(v3.x, v3.y), pkh2(v3.z, v3.w));
}

// ---------------------------------------------------------------------------
// GEMM body (R9 structure): Y[4096,1024] = (A @ W^T + bias)*oscale, fp16 pass.
// CTA 128x128, BK=64 (128B rows, SW128), 8 warps (32x64), 3-stage pipeline,
// ONE barrier per chunk; compute FIRST, prefetch AFTER (LSU ordering!).
// ---------------------------------------------------------------------------
template<int OUT>
__device__ __forceinline__ void gemm_body(
    const __half* __restrict__ A, const __half* __restrict__ B,
    const float* __restrict__ bias, void* __restrict__ Y0,
    uint32_t sb, int bm, int bn, float oscale)
{
    constexpr int PART  = 16384;    // 128 rows x 64 halves (128 B/row)
    constexpr int STAGE = 2 * PART;

    const int t = threadIdx.x, lane = t & 31, wid = t >> 5;
    const int wm = wid & 3, wn = wid >> 2;
    const int lm = lane & 7;
    const int q1 = (lane >> 3) & 1, q2 = lane >> 4;

    float acc[2][8][4];
#pragma unroll
    for (int mf = 0; mf < 2; mf++)
#pragma unroll
        for (int nf = 0; nf < 8; nf++)
#pragma unroll
            for (int j = 0; j < 4; j++) acc[mf][nf][j] = 0.0f;

    auto issue = [&](int stg, int kt) {
        const int k0 = kt * 64;
#pragma unroll
        for (int p = 0; p < 2; p++) {
            uint32_t base = sb + stg * STAGE + p * PART;
            const __half* s = p ? B : A;
            const int rb = p ? bn : bm;
#pragma unroll
            for (int i = 0; i < 4; i++) {
                int c = t + 256 * i;
                uint32_t row = c >> 3, ch = c & 7;
                uint32_t dst = base + sw_row128(row, ch * 16);
                const void* g = s + (size_t)(rb + row) * CC + k0 + ch * 8;
                CP_ASYNC_16(dst, g);
            }
        }
    };

    // Hoisted ldsm addressing (row&7 == lm for every fragment this lane reads)
    const uint32_t swl = (uint32_t)lm << 4;
    uint32_t aR[2], bR[4], cw[4];
#pragma unroll
    for (int mf = 0; mf < 2; mf++)
        aR[mf] = (uint32_t)(wm * 32 + mf * 16 + q1 * 8 + lm) * 128u;
#pragma unroll
    for (int g = 0; g < 4; g++)
        bR[g] = (uint32_t)PART + (uint32_t)(wn * 64 + g * 16 + q1 * 8 + lm) * 128u;
#pragma unroll
    for (int ks = 0; ks < 4; ks++)
        cw[ks] = ((uint32_t)(ks * 2 + q2) * 16u) ^ swl;

    auto compute = [&](int stg) {
        const uint32_t Ab = sb + stg * STAGE;
#pragma unroll
        for (int ks = 0; ks < 4; ks++) {
            uint32_t ah[2][4], bh[4][4];
#pragma unroll
            for (int mf = 0; mf < 2; mf++)
                ldsm4(ah[mf], Ab + aR[mf] + cw[ks]);
#pragma unroll
            for (int g = 0; g < 4; g++)
                ldsm4(bh[g], Ab + bR[g] + cw[ks]);
#pragma unroll
            for (int mf = 0; mf < 2; mf++)
#pragma unroll
                for (int g = 0; g < 4; g++) {
                    mma16816(acc[mf][2 * g],     ah[mf], bh[g][0], bh[g][2]);
                    mma16816(acc[mf][2 * g + 1], ah[mf], bh[g][1], bh[g][3]);
                }
        }
    };

    issue(0, 0); CP_COMMIT();
    issue(1, 1); CP_COMMIT();
    for (int kt = 0; kt < 16; kt++) {
        if (kt == 15) CP_WAIT(0); else CP_WAIT(1);
        __syncthreads();
        compute(kt % 3);
        if (kt + 2 < 16) { issue((kt + 2) % 3, kt + 2); CP_COMMIT(); }
    }

    // Epilogue
#pragma unroll
    for (int mf = 0; mf < 2; mf++) {
        const int r0 = bm + wm * 32 + mf * 16 + (lane >> 2);
#pragma unroll
        for (int nf = 0; nf < 8; nf++) {
            const int col = bn + wn * 64 + nf * 8 + (lane & 3) * 2;
            const float b0 = bias[col], b1 = bias[col + 1];
            float y0 = (acc[mf][nf][0] + b0) * oscale, y1 = (acc[mf][nf][1] + b1) * oscale;
            float y2 = (acc[mf][nf][2] + b0) * oscale, y3 = (acc[mf][nf][3] + b1) * oscale;
            if (OUT == 0) {
                *(float2*)((float*)Y0 + (size_t)r0 * CC + col)       = make_float2(y0, y1);
                *(float2*)((float*)Y0 + (size_t)(r0 + 8) * CC + col) = make_float2(y2, y3);
            } else {
                *(__half2*)((__half*)Y0 + (size_t)r0 * CC + col)       = __floats2half2_rn(y0, y1);
                *(__half2*)((__half*)Y0 + (size_t)(r0 + 8) * CC + col) = __floats2half2_rn(y2, y3);
            }
        }
    }
}

// Fused Q/K/V projection: grid (8, 32, 3); z selects problem.
__global__ __launch_bounds__(256) void gemm_qkv(
    const __half* __restrict__ q16, const __half* __restrict__ x16,
    const __half* __restrict__ wq, const __half* __restrict__ wk,
    const __half* __restrict__ wv,
    const float* __restrict__ bq, const float* __restrict__ bk,
    const float* __restrict__ bv,
    __half* __restrict__ Yq, __half* __restrict__ Yk, __half* __restrict__ Yv)
{
    extern __shared__ char smraw[];
    const uint32_t sb = smem_u32(smraw);
    const __half* A; const __half* B; const float* bias; __half* Y;
    float oscale = 1.0f;
    switch (blockIdx.z) {
        case 0:  A = q16; B = wq; bias = bq; Y = Yq; oscale = SL2E; break;
        case 1:  A = x16; B = wk; bias = bk; Y = Yk; break;
        default: A = x16; B = wv; bias = bv; Y = Yv; break;
    }
    gemm_body<1>(A, B, bias, Y, sb, blockIdx.y * 128, blockIdx.x * 128, oscale);
}

// Output projection: grid (8, 32), fp32 out.
__global__ __launch_bounds__(256) void gemm_out(
    const __half* __restrict__ A, const __half* __restrict__ B,
    const float* __restrict__ bias, float* __restrict__ Y)
{
    extern __shared__ char smraw[];
    const uint32_t sb = smem_u32(smraw);
    gemm_body<0>(A, B, bias, Y, sb, blockIdx.y * 128, blockIdx.x * 128, 1.0f);
}

// ---------------------------------------------------------------------------
// Flash attention (R9 structure) — deferred-PV schedule: per iter QK(t),
// PV(t-1), softmax(t); prefetch issued at END of iter (after ldsm drains).
// 4-stage K/V ring (64KB), one barrier per tile, Q a-frags from global.
// Grid (32, 16, 2), 128 threads.
// ---------------------------------------------------------------------------
__global__ __launch_bounds__(128) void flash_mma(
    const __half* __restrict__ Q, const __half* __restrict__ K,
    const __half* __restrict__ V, __half* __restrict__ AO)
{
    extern __shared__ char smraw[];
    const uint32_t sb = smem_u32(smraw);

    const int t = threadIdx.x, lane = t & 31, wid = t >> 5;
    const int qt = blockIdx.x, h = blockIdx.y, b = blockIdx.z;
    const int lm = lane & 7;
    const int q1 = (lane >> 3) & 1, q2 = lane >> 4;
    const size_t hcol = (size_t)h * 64;
    const size_t rowQ = (size_t)(b * NN + qt * 64);

    const __half* srcs[2] = {K, V};
    auto issue = [&](int stg, int kt) {
        uint32_t base0 = sb + stg * 16384;
#pragma unroll
        for (int p = 0; p < 2; p++) {
            uint32_t base = base0 + p * 8192;
            const __half* s = srcs[p];
#pragma unroll
            for (int i = 0; i < 4; i++) {
                int c = t + 128 * i;
                uint32_t row = c >> 3, ch = c & 7;
                uint32_t dst = base + sw_row128(row, ch * 16);
                const void* g = s + (size_t)(b * NN + kt * 64 + row) * CC + hcol + ch * 8;
                CP_ASYNC_16(dst, g);
            }
        }
    };
    issue(0, 0); CP_COMMIT();
    issue(1, 1); CP_COMMIT();

    // Q a-frags straight from global
    uint32_t aq[4][4];
    {
        const __half* qp = Q + (rowQ + wid * 16 + (lane >> 2)) * CC + hcol + (lane & 3) * 2;
#pragma unroll
        for (int ks = 0; ks < 4; ks++) {
            aq[ks][0] = *(const uint32_t*)(qp + ks * 16);
            aq[ks][1] = *(const uint32_t*)(qp + 8 * CC + ks * 16);
            aq[ks][2] = *(const uint32_t*)(qp + ks * 16 + 8);
            aq[ks][3] = *(const uint32_t*)(qp + 8 * CC + ks * 16 + 8);
        }
    }

    // Hoisted ldsm addressing (row&7 == lm everywhere)
    const uint32_t swl = (uint32_t)lm << 4;
    uint32_t kR[4], vR[4], cw[4], cv[4];
#pragma unroll
    for (int g = 0; g < 4; g++)
        kR[g] = (uint32_t)(g * 16 + q1 * 8 + lm) * 128u;
#pragma unroll
    for (int ks = 0; ks < 4; ks++)
        vR[ks] = 8192u + (uint32_t)(ks * 16 + q1 * 8 + lm) * 128u;
#pragma unroll
    for (int ks = 0; ks < 4; ks++)
        cw[ks] = ((uint32_t)(ks * 2 + q2) * 16u) ^ swl;
#pragma unroll
    for (int g = 0; g < 4; g++)
        cv[g] = ((uint32_t)(g * 2 + q2) * 16u) ^ swl;

    float o[8][4];
#pragma unroll
    for (int nf = 0; nf < 8; nf++)
#pragma unroll
        for (int j = 0; j < 4; j++) o[nf][j] = 0.0f;
    float lsum[4] = {0.0f, 0.0f, 0.0f, 0.0f};
    const uint32_t ONES2 = 0x3C003C00u;

    uint32_t apA[4][4], apB[4][4];
    uint32_t prevKb = 0;

    auto iter = [&](int kt, uint32_t (*apW)[4], uint32_t (*apR)[4], bool doPV) {
        const int cur = kt & 3;
        if (kt == 31) CP_WAIT(0); else CP_WAIT(1);
        __syncthreads();
        const uint32_t Kb = sb + cur * 16384;

        // S = Q @ K^T
        float s[8][4];
#pragma unroll
        for (int nf = 0; nf < 8; nf++)
#pragma unroll
            for (int j = 0; j < 4; j++) s[nf][j] = 0.0f;
#pragma unroll
        for (int ks = 0; ks < 4; ks++) {
            uint32_t bk[4][4];
#pragma unroll
            for (int g = 0; g < 4; g++)
                ldsm4(bk[g], Kb + kR[g] + cw[ks]);
#pragma unroll
            for (int g = 0; g < 4; g++) {
                mma16816(s[2 * g],     aq[ks], bk[g][0], bk[g][2]);
                mma16816(s[2 * g + 1], aq[ks], bk[g][1], bk[g][3]);
            }
        }

        // Deferred PV(t-1)
        if (doPV) {
#pragma unroll
            for (int ks = 0; ks < 4; ks++) {
                uint32_t bv[4][4];
#pragma unroll
                for (int g = 0; g < 4; g++)
                    ldsm4t(bv[g], prevKb + vR[ks] + cv[g]);
#pragma unroll
                for (int g = 0; g < 4; g++) {
                    mma16816(o[2 * g],     apR[ks], bv[g][0], bv[g][1]);
                    mma16816(o[2 * g + 1], apR[ks], bv[g][2], bv[g][3]);
                }
            }
        }

        // softmax(t)
#pragma unroll
        for (int tt = 0; tt < 4; tt++) {
            apW[tt][0] = h2ex2(pkh2(s[2 * tt][0],     s[2 * tt][1]));
            apW[tt][1] = h2ex2(pkh2(s[2 * tt][2],     s[2 * tt][3]));
            apW[tt][2] = h2ex2(pkh2(s[2 * tt + 1][0], s[2 * tt + 1][1]));
            apW[tt][3] = h2ex2(pkh2(s[2 * tt + 1][2], s[2 * tt + 1][3]));
        }
#pragma unroll
        for (int ks = 0; ks < 4; ks++)
            mma16816(lsum, apW[ks], ONES2, ONES2);

        prevKb = Kb;
        if (kt + 2 < 32) { issue((kt + 2) & 3, kt + 2); CP_COMMIT(); }
    };

    iter(0, apA, apB, false);
    iter(1, apB, apA, true);
    for (int kt2 = 1; kt2 < 16; kt2++) {
        iter(2 * kt2,     apA, apB, true);
        iter(2 * kt2 + 1, apB, apA, true);
    }
    // Final PV for tile 31
#pragma unroll
    for (int ks = 0; ks < 4; ks++) {
        uint32_t bv[4][4];
#pragma unroll
        for (int g = 0; g < 4; g++)
            ldsm4t(bv[g], prevKb + vR[ks] + cv[g]);
#pragma unroll
        for (int g = 0; g < 4; g++) {
            mma16816(o[2 * g],     apB[ks], bv[g][0], bv[g][1]);
            mma16816(o[2 * g + 1], apB[ks], bv[g][2], bv[g][3]);
        }
    }

    // Epilogue: normalize, emit fp16
    const float i0 = 1.0f / lsum[0], i1 = 1.0f / lsum[2];
    const size_t ro = (rowQ + wid * 16 + (lane >> 2)) * CC + hcol;
#pragma unroll
    for (int nf = 0; nf < 8; nf++) {
        const int col = nf * 8 + (lane & 3) * 2;
        *(__half2*)&AO[ro + col]          = __floats2half2_rn(o[nf][0] * i0, o[nf][1] * i0);
        *(__half2*)&AO[ro + 8 * CC + col] = __floats2half2_rn(o[nf][2] * i1, o[nf][3] * i1);
    }
}

// ---------------------------------------------------------------------------
extern "C" void kernel_launch(void* const* d_in, const int* in_sizes, int n_in,
                              void* d_out, int out_size)
{
    const float* x       = (const float*)d_in[0];
    const float* queries = (const float*)d_in[1];
    const float* wq = (const float*)d_in[2];
    const float* bq = (const float*)d_in[3];
    const float* wk = (const float*)d_in[4];
    const float* bk = (const float*)d_in[5];
    const float* wv = (const float*)d_in[6];
    const float* bv = (const float*)d_in[7];
    const float* wo = (const float*)d_in[8];
    const float* bo = (const float*)d_in[9];
    float* out = (float*)d_out;

    __half *q16, *x16, *wq16, *wk16, *wv16, *wo16, *ao16, *Qp, *Kp, *Vp;
    cudaGetSymbolAddress((void**)&q16,  g_q16);
    cudaGetSymbolAddress((void**)&x16,  g_x16);
    cudaGetSymbolAddress((void**)&wq16, g_wq16);
    cudaGetSymbolAddress((void**)&wk16, g_wk16);
    cudaGetSymbolAddress((void**)&wv16, g_wv16);
    cudaGetSymbolAddress((void**)&wo16, g_wo16);
    cudaGetSymbolAddress((void**)&ao16, g_ao16);
    cudaGetSymbolAddress((void**)&Qp,   g_Qp);
    cudaGetSymbolAddress((void**)&Kp,   g_Kp);
    cudaGetSymbolAddress((void**)&Vp,   g_V16);

    const int gsmem = 3 * 32768;   // 98304
    cudaFuncSetAttribute(gemm_qkv, cudaFuncAttributeMaxDynamicSharedMemorySize, gsmem);
    cudaFuncSetAttribute(gemm_out, cudaFuncAttributeMaxDynamicSharedMemorySize, gsmem);
    cudaFuncSetAttribute(flash_mma, cudaFuncAttributeMaxDynamicSharedMemorySize, 65536);

    const int nX4 = MM * CC / 4;   // 1M
    const int nW4 = CC * CC / 4;   // 256K
    cvt_all_k<<<(2 * nX4 + 4 * nW4) / 1024, 256>>>(
        x, queries, wq, wk, wv, wo, x16, q16, wq16, wk16, wv16, wo16);

    gemm_qkv<<<dim3(8, 32, 3), 256, gsmem>>>(q16, x16, wq16, wk16, wv16,
                                             bq, bk, bv, Qp, Kp, Vp);

    flash_mma<<<dim3(NN / 64, HH, BB), 128, 65536>>>(Qp, Kp, Vp, ao16);

    gemm_out<<<dim3(8, 32), 256, gsmem>>>(ao16, wo16, bo, out);
}